// round 8
// baseline (speedup 1.0000x reference)
#include <cuda_runtime.h>
#include <cuda_fp16.h>
#include <stdint.h>

#define N_NODES 100000
#define BATCH   50000
#define K       10
#define DIM     128

// fp16 feature table: 25.6 MB (L2-resident hot set).
__device__ __half g_tab16[N_NODES * DIM];

// ---------------------------------------------------------------------------
// Pass 1: fp32 -> fp16. One thread = 32B of table (16 halfs), i.e. 4 float4
// reads + 2 uint4 writes. 800k threads total.
// ---------------------------------------------------------------------------
__global__ __launch_bounds__(256) void convert_kernel(const float4* __restrict__ feat)
{
    const int i = blockIdx.x * blockDim.x + threadIdx.x;
    const int n32 = N_NODES * DIM / 16;                 // 800k
    if (i >= n32) return;

    float4 a = __ldg(&feat[i * 4 + 0]);
    float4 b = __ldg(&feat[i * 4 + 1]);
    float4 c = __ldg(&feat[i * 4 + 2]);
    float4 d = __ldg(&feat[i * 4 + 3]);

    __half2 h0 = __float22half2_rn(make_float2(a.x, a.y));
    __half2 h1 = __float22half2_rn(make_float2(a.z, a.w));
    __half2 h2 = __float22half2_rn(make_float2(b.x, b.y));
    __half2 h3 = __float22half2_rn(make_float2(b.z, b.w));
    __half2 h4 = __float22half2_rn(make_float2(c.x, c.y));
    __half2 h5 = __float22half2_rn(make_float2(c.z, c.w));
    __half2 h6 = __float22half2_rn(make_float2(d.x, d.y));
    __half2 h7 = __float22half2_rn(make_float2(d.z, d.w));

    uint4 p0, p1;
    p0.x = *reinterpret_cast<unsigned*>(&h0);
    p0.y = *reinterpret_cast<unsigned*>(&h1);
    p0.z = *reinterpret_cast<unsigned*>(&h2);
    p0.w = *reinterpret_cast<unsigned*>(&h3);
    p1.x = *reinterpret_cast<unsigned*>(&h4);
    p1.y = *reinterpret_cast<unsigned*>(&h5);
    p1.z = *reinterpret_cast<unsigned*>(&h6);
    p1.w = *reinterpret_cast<unsigned*>(&h7);

    uint4* dst = reinterpret_cast<uint4*>(g_tab16);
    dst[i * 2 + 0] = p0;
    dst[i * 2 + 1] = p1;
}

// ---------------------------------------------------------------------------
// Pass 2: gather-mean. One warp per row; lane owns 4 columns (uint2 = 8B of
// the 256B fp16 row). Index fetch is lane-parallel + shfl broadcast (2-sector
// coalesced load instead of 11 serial scalar loads). All 11 gathered loads
// front-batched; inner loop is pure HADD2.
// ---------------------------------------------------------------------------
__global__ __launch_bounds__(256) void gather_kernel(
    const int* __restrict__ nodes,
    const int* __restrict__ neighbours,
    float4* __restrict__ out)
{
    const int warp = (blockIdx.x * blockDim.x + threadIdx.x) >> 5;
    const int lane = threadIdx.x & 31;
    if (warp >= BATCH) return;

    // Lanes 0..K cooperatively fetch the 11 ids, then broadcast via shfl.
    int my = 0;
    if (lane == 0)      my = nodes[warp];
    else if (lane <= K) my = neighbours[warp * K + (lane - 1)];

    int idx[K + 1];
#pragma unroll
    for (int k = 0; k < K + 1; k++)
        idx[k] = __shfl_sync(0xFFFFFFFFu, my, k);

    const uint2* __restrict__ tab = reinterpret_cast<const uint2*>(g_tab16);

    // Front-batch all 11 gathered 8B loads (row stride = 256B = 32 uint2).
    uint2 v[K + 1];
#pragma unroll
    for (int k = 0; k < K + 1; k++)
        v[k] = __ldg(&tab[idx[k] * 32 + lane]);

    __half2 acc01 = *reinterpret_cast<__half2*>(&v[0].x);
    __half2 acc23 = *reinterpret_cast<__half2*>(&v[0].y);
#pragma unroll
    for (int k = 1; k < K + 1; k++) {
        acc01 = __hadd2(acc01, *reinterpret_cast<__half2*>(&v[k].x));
        acc23 = __hadd2(acc23, *reinterpret_cast<__half2*>(&v[k].y));
    }

    const float s = 1.0f / (float)(K + 1);
    float2 f01 = __half22float2(acc01);
    float2 f23 = __half22float2(acc23);

    float4 o;
    o.x = f01.x * s;
    o.y = f01.y * s;
    o.z = f23.x * s;
    o.w = f23.y * s;
    __stcs(&out[warp * 32 + lane], o);   // write-once: stream past L2
}

extern "C" void kernel_launch(void* const* d_in, const int* in_sizes, int n_in,
                              void* d_out, int out_size)
{
    const int*    nodes      = (const int*)d_in[0];
    const int*    neighbours = (const int*)d_in[1];
    const float4* features   = (const float4*)d_in[2];
    float4*       out        = (float4*)d_out;

    const int n32 = N_NODES * DIM / 16;
    convert_kernel<<<(n32 + 255) / 256, 256>>>(features);

    const int warps_per_block = 256 / 32;
    const int blocks = (BATCH + warps_per_block - 1) / warps_per_block;
    gather_kernel<<<blocks, 256>>>(nodes, neighbours, out);
}